// round 3
// baseline (speedup 1.0000x reference)
#include <cuda_runtime.h>
#include <math.h>

#define NN 50000
#define NE 800000
#define FD 128
#define NC 40

// Scratch (device globals: allocation-free per harness rules)
__device__ __align__(16) float g_agg[(size_t)NN * FD];
__device__ __align__(16) float g_h[(size_t)NN * FD];
__device__ float g_deg[NN];

// ---- packed f32x2 helpers (Blackwell dual-fp32 pipe) ----
__device__ __forceinline__ unsigned long long pk2(float lo, float hi) {
    unsigned long long r;
    asm("mov.b64 %0, {%1, %2};" : "=l"(r) : "f"(lo), "f"(hi));
    return r;
}
__device__ __forceinline__ unsigned long long fma2(unsigned long long a,
                                                   unsigned long long b,
                                                   unsigned long long c) {
    unsigned long long d;
    asm("fma.rn.f32x2 %0, %1, %2, %3;" : "=l"(d) : "l"(a), "l"(b), "l"(c));
    return d;
}
__device__ __forceinline__ void unpk(unsigned long long v, float& lo, float& hi) {
    asm("mov.b64 {%0, %1}, %2;" : "=f"(lo), "=f"(hi) : "l"(v));
}

// ---- zero agg (and optionally deg) ----
__global__ void zero_kernel(int zero_deg) {
    int i = blockIdx.x * blockDim.x + threadIdx.x;
    if (i < NN * FD / 4)
        reinterpret_cast<float4*>(g_agg)[i] = make_float4(0.f, 0.f, 0.f, 0.f);
    if (zero_deg && i < NN) g_deg[i] = 0.f;
}

// ---- edge scatter: one warp per edge, float4 gather + v4 reduction ----
__global__ void scatter_kernel(const float* __restrict__ x_in,
                               const int* __restrict__ ei,
                               int with_deg, int use_h) {
    const float* __restrict__ feat = use_h ? (const float*)g_h : x_in;
    int lane = threadIdx.x & 31;
    int wid = (blockIdx.x * blockDim.x + threadIdx.x) >> 5;
    int nw = (gridDim.x * blockDim.x) >> 5;
    for (int e = wid; e < NE; e += nw) {
        int src = __ldg(ei + e);
        int dst = __ldg(ei + NE + e);
        float4 v = __ldg(reinterpret_cast<const float4*>(feat) + src * 32 + lane);
        float* dp = g_agg + (size_t)dst * FD + lane * 4;
        asm volatile("red.global.add.v4.f32 [%0], {%1,%2,%3,%4};"
                     :: "l"(dp), "f"(v.x), "f"(v.y), "f"(v.z), "f"(v.w)
                     : "memory");
        if (with_deg && lane == 0) atomicAdd(g_deg + dst, 1.0f);
    }
}

// ---- layer 1: h = relu( (agg/deg)@W1_l + x@W1_r + b1 ), 32 nodes/block ----
__global__ __launch_bounds__(256, 2) void sage1_kernel(
    const float* __restrict__ x,
    const float* __restrict__ Wl,
    const float* __restrict__ Wr,
    const float* __restrict__ b) {
    __shared__ float s_a[32 * FD];
    __shared__ float s_x[32 * FD];
    __shared__ float s_inv[32];
    int tid = threadIdx.x;
    int nb = blockIdx.x * 32;

    if (tid < 32) {
        int n = nb + tid;
        float d = (n < NN) ? g_deg[n] : 1.f;
        s_inv[tid] = 1.f / fmaxf(d, 1.f);
    }
    __syncthreads();
    for (int idx = tid; idx < 32 * FD; idx += 256) {
        int n = idx >> 7;
        int node = nb + n;
        float a = 0.f, xv = 0.f;
        if (node < NN) {
            int k = idx & 127;
            a = g_agg[(size_t)node * FD + k] * s_inv[n];
            xv = x[(size_t)node * FD + k];
        }
        s_a[idx] = a;
        s_x[idx] = xv;
    }
    __syncthreads();

    int ty = tid >> 5, tx = tid & 31;
    int c0 = tx * 4;         // 4 output cols per thread
    int nl = ty * 4;         // 4 nodes per thread (2 f32x2 pairs)

    unsigned long long acc[2][4];
#pragma unroll
    for (int j = 0; j < 4; ++j) {
        float bj = __ldg(b + c0 + j);
        unsigned long long bb = pk2(bj, bj);
        acc[0][j] = bb;
        acc[1][j] = bb;
    }

#pragma unroll 4
    for (int k = 0; k < FD; ++k) {
        float4 wl = __ldg(reinterpret_cast<const float4*>(Wl + (size_t)k * FD) + tx);
        float4 wr = __ldg(reinterpret_cast<const float4*>(Wr + (size_t)k * FD) + tx);
        unsigned long long wlp[4] = {pk2(wl.x, wl.x), pk2(wl.y, wl.y),
                                     pk2(wl.z, wl.z), pk2(wl.w, wl.w)};
        unsigned long long wrp[4] = {pk2(wr.x, wr.x), pk2(wr.y, wr.y),
                                     pk2(wr.z, wr.z), pk2(wr.w, wr.w)};
#pragma unroll
        for (int p = 0; p < 2; ++p) {
            int base = (nl + 2 * p) * FD + k;
            unsigned long long ap = pk2(s_a[base], s_a[base + FD]);
            unsigned long long xp = pk2(s_x[base], s_x[base + FD]);
#pragma unroll
            for (int j = 0; j < 4; ++j) {
                acc[p][j] = fma2(ap, wlp[j], acc[p][j]);
                acc[p][j] = fma2(xp, wrp[j], acc[p][j]);
            }
        }
    }

#pragma unroll
    for (int p = 0; p < 2; ++p) {
        float lo[4], hi[4];
#pragma unroll
        for (int j = 0; j < 4; ++j) unpk(acc[p][j], lo[j], hi[j]);
        int node0 = nb + nl + 2 * p;
        if (node0 < NN) {
            float4 v = make_float4(fmaxf(lo[0], 0.f), fmaxf(lo[1], 0.f),
                                   fmaxf(lo[2], 0.f), fmaxf(lo[3], 0.f));
            *reinterpret_cast<float4*>(g_h + (size_t)node0 * FD + c0) = v;
        }
        if (node0 + 1 < NN) {
            float4 v = make_float4(fmaxf(hi[0], 0.f), fmaxf(hi[1], 0.f),
                                   fmaxf(hi[2], 0.f), fmaxf(hi[3], 0.f));
            *reinterpret_cast<float4*>(g_h + (size_t)(node0 + 1) * FD + c0) = v;
        }
    }
}

// ---- layer 2 + relu + log_softmax, 32 nodes/block ----
__global__ __launch_bounds__(256, 2) void sage2_kernel(
    const float* __restrict__ Wl,
    const float* __restrict__ Wr,
    const float* __restrict__ b,
    float* __restrict__ out) {
    __shared__ float s_a[32 * FD];
    __shared__ float s_h[32 * FD];
    __shared__ float s_inv[32];
    int tid = threadIdx.x;
    int nb = blockIdx.x * 32;

    if (tid < 32) {
        int n = nb + tid;
        float d = (n < NN) ? g_deg[n] : 1.f;
        s_inv[tid] = 1.f / fmaxf(d, 1.f);
    }
    __syncthreads();
    for (int idx = tid; idx < 32 * FD; idx += 256) {
        int n = idx >> 7;
        int node = nb + n;
        float a = 0.f, hv = 0.f;
        if (node < NN) {
            int k = idx & 127;
            a = g_agg[(size_t)node * FD + k] * s_inv[n];
            hv = g_h[(size_t)node * FD + k];
        }
        s_a[idx] = a;
        s_h[idx] = hv;
    }
    __syncthreads();

    int ty = tid >> 5, tx = tid & 31;
    bool active = (tx < 20);         // 20 lanes x 2 cols = 40 classes
    int cx = active ? tx : 19;       // clamp: inactive lanes compute dupes
    int c0 = cx * 2;
    int nl = ty * 4;

    unsigned long long acc[2][2];
    {
        float b0 = __ldg(b + c0), b1 = __ldg(b + c0 + 1);
        acc[0][0] = pk2(b0, b0);
        acc[1][0] = pk2(b0, b0);
        acc[0][1] = pk2(b1, b1);
        acc[1][1] = pk2(b1, b1);
    }

#pragma unroll 4
    for (int k = 0; k < FD; ++k) {
        float2 wl = __ldg(reinterpret_cast<const float2*>(Wl + (size_t)k * NC) + cx);
        float2 wr = __ldg(reinterpret_cast<const float2*>(Wr + (size_t)k * NC) + cx);
        unsigned long long wl0 = pk2(wl.x, wl.x), wl1 = pk2(wl.y, wl.y);
        unsigned long long wr0 = pk2(wr.x, wr.x), wr1 = pk2(wr.y, wr.y);
#pragma unroll
        for (int p = 0; p < 2; ++p) {
            int base = (nl + 2 * p) * FD + k;
            unsigned long long ap = pk2(s_a[base], s_a[base + FD]);
            unsigned long long hp = pk2(s_h[base], s_h[base + FD]);
            acc[p][0] = fma2(ap, wl0, acc[p][0]);
            acc[p][0] = fma2(hp, wr0, acc[p][0]);
            acc[p][1] = fma2(ap, wl1, acc[p][1]);
            acc[p][1] = fma2(hp, wr1, acc[p][1]);
        }
    }

    // relu + per-node log_softmax over 40 values spread across 20 lanes
#pragma unroll
    for (int p = 0; p < 2; ++p) {
        float z00, z10, z01, z11;
        unpk(acc[p][0], z00, z10);   // col c0:   node n0 / n1
        unpk(acc[p][1], z01, z11);   // col c0+1: node n0 / n1
        z00 = fmaxf(z00, 0.f); z01 = fmaxf(z01, 0.f);
        z10 = fmaxf(z10, 0.f); z11 = fmaxf(z11, 0.f);

        int n0 = nb + nl + 2 * p;
#pragma unroll
        for (int q = 0; q < 2; ++q) {
            float za = q ? z10 : z00;
            float zb = q ? z11 : z01;
            int node = n0 + q;
            float m = active ? fmaxf(za, zb) : -3.0e38f;
#pragma unroll
            for (int o = 16; o > 0; o >>= 1)
                m = fmaxf(m, __shfl_xor_sync(0xffffffffu, m, o));
            float s = active ? (expf(za - m) + expf(zb - m)) : 0.f;
#pragma unroll
            for (int o = 16; o > 0; o >>= 1)
                s += __shfl_xor_sync(0xffffffffu, s, o);
            float lse = m + logf(s);
            if (active && node < NN) {
                out[(size_t)node * NC + 2 * tx] = za - lse;
                out[(size_t)node * NC + 2 * tx + 1] = zb - lse;
            }
        }
    }
}

extern "C" void kernel_launch(void* const* d_in, const int* in_sizes, int n_in,
                              void* d_out, int out_size) {
    const float* x   = (const float*)d_in[0];
    const int*   ei  = (const int*)d_in[1];
    const float* W1l = (const float*)d_in[2];
    const float* W1r = (const float*)d_in[3];
    const float* b1  = (const float*)d_in[4];
    const float* W2l = (const float*)d_in[5];
    const float* W2r = (const float*)d_in[6];
    const float* b2  = (const float*)d_in[7];
    float* out = (float*)d_out;

    const int ZB = (NN * FD / 4 + 255) / 256;   // 6250
    const int SB = 1184;                        // 8 blocks/SM scatter grid
    const int GB = (NN + 31) / 32;              // 1563

    zero_kernel<<<ZB, 256>>>(1);
    scatter_kernel<<<SB, 256>>>(x, ei, /*with_deg=*/1, /*use_h=*/0);
    sage1_kernel<<<GB, 256>>>(x, W1l, W1r, b1);
    zero_kernel<<<ZB, 256>>>(0);
    scatter_kernel<<<SB, 256>>>(x, ei, /*with_deg=*/0, /*use_h=*/1);
    sage2_kernel<<<GB, 256>>>(W2l, W2r, b2, out);
}